// round 10
// baseline (speedup 1.0000x reference)
#include <cuda_runtime.h>
#include <math.h>
#include <float.h>

#define EE       64
#define TOPK_    8
#define BM       128
#define BK       16
#define NTHREADS 512
#define NCH      128      // D / BK
#define SPLIT_CH 63       // Eigen gebp kc = 1016 = 63*16 + 8
#define SPLIT_K  8

// packed fp32x2 ops (two IEEE fp32 lanes; identical rounding to scalar FFMA/FADD)
#define FMA2(d, a, b) asm("fma.rn.f32x2 %0, %1, %2, %0;" : "+l"(d) : "l"(a), "l"(b))
#define ADD2(d, a)    asm("add.rn.f32x2 %0, %0, %1;"     : "+l"(d) : "l"(a))

// Correctly-rounded-class fp32 sigmoid (float-float, ~2^-40 internal) — DO NOT TOUCH:
// this exact function passed round 9.
__device__ __forceinline__ float sigmoid_cr(float x)
{
    float z = -x;
    z = fminf(fmaxf(z, -80.0f), 80.0f);
    const float n = rintf(z * 1.4426950408889634f);
    float r = fmaf(-n, 0.693145751953125f, z);
    r = fmaf(-n, 1.4286068203e-06f, r);
    const float r2 = r * r;
    float p = 2.7557319e-6f;
    p = fmaf(p, r, 2.4801587e-5f);
    p = fmaf(p, r, 1.9841270e-4f);
    p = fmaf(p, r, 1.3888889e-3f);
    p = fmaf(p, r, 8.3333333e-3f);
    p = fmaf(p, r, 4.1666667e-2f);
    p = fmaf(p, r, 1.6666667e-1f);
    p = fmaf(p, r, 0.5f);
    const float q = r2 * p;
    const float s1 = 1.0f + r;
    const float e1 = (1.0f - s1) + r;
    const float s2 = s1 + q;
    const float e2 = (s1 - s2) + q;
    const float elo = e1 + e2;
    const float sc = __int_as_float(((int)n + 127) << 23);
    const float Eh = s2 * sc;
    const float El = elo * sc;
    const float th = 1.0f + Eh;
    const float ap = th - Eh;
    const float bp = th - ap;
    const float tl = ((1.0f - ap) + (Eh - bp)) + El;
    const float y0 = __fdiv_rn(1.0f, th);
    float rr = fmaf(-y0, th, 1.0f);
    rr = fmaf(-y0, tl, rr);
    return fmaf(y0, rr, y0);
}

struct Tile {
    float2 xs[BK][BM];   // x duplicated (v,v); col = tok ^ (4*(k>>2)) swizzle. 16 KB
    float  ws[BK][EE];   // w natural order (adjacent experts = f32x2 pair).   4 KB
};

union GateSm {
    Tile  t[2];                // 40 KB double buffer
    float sc[BM][EE + 2];      // 33.8 KB sigmoid scores (aliases tiles after GEMM)
};

template<bool SPL>
__device__ __forceinline__ void compute_chunk(
    const Tile& tb,
    unsigned long long (&acc)[4][2], unsigned long long (&accS)[4][2],
    int tx, int ty)
{
#pragma unroll
    for (int k = 0; k < BK; ++k) {
        if (SPL && k == SPLIT_K) {   // global k == 1016: bank panel A, restart chain
#pragma unroll
            for (int t = 0; t < 4; ++t)
#pragma unroll
                for (int e = 0; e < 2; ++e) { accS[t][e] = acc[t][e]; acc[t][e] = 0ull; }
        }
        const int s = (k >> 2) & 3;
        const float2* xr = &tb.xs[k][(ty ^ s) * 4];
        const ulonglong2 xa = *(const ulonglong2*)(xr);       // tokens 4ty+0,1 (dup)
        const ulonglong2 xb = *(const ulonglong2*)(xr + 2);   // tokens 4ty+2,3 (dup)
        const ulonglong2 wv = *(const ulonglong2*)(&tb.ws[k][tx * 4]); // experts 4tx..4tx+3
        const unsigned long long xv0 = xa.x, xv1 = xa.y, xv2 = xb.x, xv3 = xb.y;
        FMA2(acc[0][0], wv.x, xv0); FMA2(acc[0][1], wv.y, xv0);
        FMA2(acc[1][0], wv.x, xv1); FMA2(acc[1][1], wv.y, xv1);
        FMA2(acc[2][0], wv.x, xv2); FMA2(acc[2][1], wv.y, xv2);
        FMA2(acc[3][0], wv.x, xv3); FMA2(acc[3][1], wv.y, xv3);
    }
}

__global__ __launch_bounds__(NTHREADS, 1)
void gate_kernel(const float* __restrict__ x, const float* __restrict__ wgt,
                 const float* __restrict__ bias, float* __restrict__ out,
                 int N, int D)
{
    __shared__ GateSm sm;

    const int tid  = threadIdx.x;
    const int tx   = tid & 15;    // experts 4tx .. 4tx+3
    const int ty   = tid >> 4;    // tokens  4ty .. 4ty+3  (0..31)
    const int row0 = blockIdx.x * BM;

    // gmem load mapping: x — 4 consecutive threads cover one token's 16 k-values
    const int xtok = tid >> 2;    // 0..127
    const int xkq  = tid & 3;     // k-group of 4
    // w — first 256 threads: one (expert, k-group)
    const int wex  = tid >> 2;    // 0..63 (tid<256)
    const int wkq  = tid & 3;

    // chain A (banked in accS) + chain B, per (token, expert) lane — round-9 numerics
    unsigned long long acc[4][2], accS[4][2];
#pragma unroll
    for (int t = 0; t < 4; ++t)
#pragma unroll
        for (int e = 0; e < 2; ++e) { acc[t][e] = 0ull; accS[t][e] = 0ull; }

    const float* xptr = x + (size_t)(row0 + xtok) * D + xkq * 4;
    const float* wptr = wgt + (size_t)wex * D + wkq * 4;

    float4 rx = *(const float4*)xptr;
    float4 rw = make_float4(0.f, 0.f, 0.f, 0.f);
    if (tid < 256) rw = *(const float4*)wptr;

    for (int ch = 0; ch < NCH; ++ch) {
        Tile& tb = sm.t[ch & 1];

        // store x transposed + duplicated + swizzled (rows xkq*4+i share s = xkq)
        {
            const int col = xtok ^ (xkq * 4);
            tb.xs[xkq * 4 + 0][col] = make_float2(rx.x, rx.x);
            tb.xs[xkq * 4 + 1][col] = make_float2(rx.y, rx.y);
            tb.xs[xkq * 4 + 2][col] = make_float2(rx.z, rx.z);
            tb.xs[xkq * 4 + 3][col] = make_float2(rx.w, rx.w);
        }
        if (tid < 256) {
            tb.ws[wkq * 4 + 0][wex] = rw.x;
            tb.ws[wkq * 4 + 1][wex] = rw.y;
            tb.ws[wkq * 4 + 2][wex] = rw.z;
            tb.ws[wkq * 4 + 3][wex] = rw.w;
        }
        __syncthreads();   // tile ch ready; previous buffer's readers all done

        // prefetch next chunk (overlaps with compute below)
        if (ch + 1 < NCH) {
            rx = *(const float4*)(xptr + (ch + 1) * BK);
            if (tid < 256) rw = *(const float4*)(wptr + (ch + 1) * BK);
        }

        if (ch == SPLIT_CH) compute_chunk<true >(tb, acc, accS, tx, ty);
        else                compute_chunk<false>(tb, acc, accS, tx, ty);
    }

    // logit = panel A + panel B (single packed FADD — round-9 order)
#pragma unroll
    for (int t = 0; t < 4; ++t)
#pragma unroll
        for (int e = 0; e < 2; ++e)
            ADD2(accS[t][e], acc[t][e]);

    __syncthreads();   // all compute done before aliasing tiles with scores

    // sigmoid -> scores in smem. acc[t][e]: lo = expert 4tx+2e, hi = 4tx+2e+1
#pragma unroll
    for (int t = 0; t < 4; ++t) {
#pragma unroll
        for (int e = 0; e < 2; ++e) {
            const unsigned long long a = accS[t][e];
            const float lo = __uint_as_float((unsigned)a);
            const float hi = __uint_as_float((unsigned)(a >> 32));
            sm.sc[4 * ty + t][4 * tx + 2 * e]     = sigmoid_cr(lo);
            sm.sc[4 * ty + t][4 * tx + 2 * e + 1] = sigmoid_cr(hi);
        }
    }
    __syncthreads();

    // top-8 per row: one warp per row, iterative warp-argmax (tie -> smaller index)
    const int lane = tid & 31;
    const int wid  = tid >> 5;   // 0..15
    const float b0 = __ldg(&bias[lane]);
    const float b1 = __ldg(&bias[lane + 32]);
    float* outw = out;
    float* outi = out + (size_t)N * TOPK_;

    for (int rr = wid; rr < BM; rr += 16) {
        const float s0 = sm.sc[rr][lane];
        const float s1 = sm.sc[rr][lane + 32];
        float r0 = __fadd_rn(s0, b0);
        float r1 = __fadd_rn(s1, b1);

        float wsel[TOPK_];
        int   isel[TOPK_];
        float sum = 0.0f;

#pragma unroll
        for (int t = 0; t < TOPK_; ++t) {
            float v; int i;
            if (r1 > r0) { v = r1; i = lane + 32; } else { v = r0; i = lane; }
#pragma unroll
            for (int off = 16; off > 0; off >>= 1) {
                const float vo = __shfl_down_sync(0xffffffffu, v, off);
                const int   io = __shfl_down_sync(0xffffffffu, i, off);
                if (vo > v || (vo == v && io < i)) { v = vo; i = io; }
            }
            i = __shfl_sync(0xffffffffu, i, 0);
            if (i == lane)      r0 = -FLT_MAX;
            if (i == lane + 32) r1 = -FLT_MAX;
            const float orig = sm.sc[rr][i];        // original (un-biased) sigmoid score
            isel[t] = i;
            wsel[t] = orig;
            sum = __fadd_rn(sum, orig);             // sequential last-axis sum like reference
        }

        const float denom = __fadd_rn(sum, 1e-8f);  // (w / (sum+1e-8)) * 2.5, ref op order
        const int grow = row0 + rr;
#pragma unroll
        for (int t = 0; t < TOPK_; ++t) {
            if (lane == t) {
                outw[(size_t)grow * TOPK_ + t] = __fmul_rn(__fdiv_rn(wsel[t], denom), 2.5f);
                outi[(size_t)grow * TOPK_ + t] = (float)isel[t];
            }
        }
    }
}

extern "C" void kernel_launch(void* const* d_in, const int* in_sizes, int n_in,
                              void* d_out, int out_size)
{
    const float* x = (const float*)d_in[0];
    const float* w = (const float*)d_in[1];
    const float* b = (const float*)d_in[2];

    const int E = in_sizes[2];          // 64
    const int D = in_sizes[1] / E;      // 2048
    const int N = in_sizes[0] / D;      // 16384
    (void)n_in; (void)out_size; (void)E;

    dim3 grid(N / BM);
    gate_kernel<<<grid, NTHREADS>>>(x, w, b, (float*)d_out, N, D);
}

// round 12
// speedup vs baseline: 1.0952x; 1.0952x over previous
#include <cuda_runtime.h>
#include <math.h>
#include <float.h>

#define EE       64
#define TOPK_    8
#define BM       128
#define BK       32
#define NTHREADS 512
#define NCH      64       // D / BK
#define SPLIT_CH 31       // Eigen gebp kc = 1016 = 31*32 + 24
#define SPLIT_KO 24

// packed fp32x2 ops (two IEEE fp32 lanes; identical rounding to scalar FFMA/FADD)
#define FMA2(d, a, b) asm("fma.rn.f32x2 %0, %1, %2, %0;" : "+l"(d) : "l"(a), "l"(b))
#define ADD2(d, a)    asm("add.rn.f32x2 %0, %0, %1;"     : "+l"(d) : "l"(a))

// 8 packed FMAs of one k-step: acc[token][expert-pair] += w_pair * x_dup
#define FMA8(acc, xa, xb, wv) do { \
    FMA2(acc[0][0], wv.x, xa.x); FMA2(acc[0][1], wv.y, xa.x); \
    FMA2(acc[1][0], wv.x, xa.y); FMA2(acc[1][1], wv.y, xa.y); \
    FMA2(acc[2][0], wv.x, xb.x); FMA2(acc[2][1], wv.y, xb.x); \
    FMA2(acc[3][0], wv.x, xb.y); FMA2(acc[3][1], wv.y, xb.y); } while (0)

// Correctly-rounded-class fp32 sigmoid — passed rounds 9/10, DO NOT TOUCH.
__device__ __forceinline__ float sigmoid_cr(float x)
{
    float z = -x;
    z = fminf(fmaxf(z, -80.0f), 80.0f);
    const float n = rintf(z * 1.4426950408889634f);
    float r = fmaf(-n, 0.693145751953125f, z);
    r = fmaf(-n, 1.4286068203e-06f, r);
    const float r2 = r * r;
    float p = 2.7557319e-6f;
    p = fmaf(p, r, 2.4801587e-5f);
    p = fmaf(p, r, 1.9841270e-4f);
    p = fmaf(p, r, 1.3888889e-3f);
    p = fmaf(p, r, 8.3333333e-3f);
    p = fmaf(p, r, 4.1666667e-2f);
    p = fmaf(p, r, 1.6666667e-1f);
    p = fmaf(p, r, 0.5f);
    const float q = r2 * p;
    const float s1 = 1.0f + r;
    const float e1 = (1.0f - s1) + r;
    const float s2 = s1 + q;
    const float e2 = (s1 - s2) + q;
    const float elo = e1 + e2;
    const float sc = __int_as_float(((int)n + 127) << 23);
    const float Eh = s2 * sc;
    const float El = elo * sc;
    const float th = 1.0f + Eh;
    const float ap = th - Eh;
    const float bp = th - ap;
    const float tl = ((1.0f - ap) + (Eh - bp)) + El;
    const float y0 = __fdiv_rn(1.0f, th);
    float rr = fmaf(-y0, th, 1.0f);
    rr = fmaf(-y0, tl, rr);
    return fmaf(y0, rr, y0);
}

struct Tile {
    float2 xs[BK][BM];   // x duplicated (v,v); col = tok ^ (4*((k>>2)&3)).  32 KB
    float  ws[BK][EE];   // w, col group XOR-swizzled by (k>>2).              8 KB
};

struct GateSm {
    union {
        Tile  t[2];              // 80 KB double buffer
        float sc[BM][EE + 2];    // sigmoid scores (aliases tiles after GEMM)
    };
};

template<bool SPL>
__device__ __forceinline__ void compute_chunk(
    const Tile& tb,
    unsigned long long (&acc)[4][2], unsigned long long (&accS)[4][2],
    int tx, int ty)
{
    ulonglong2 xaA, xbA, wvA, xaB, xbB, wvB;
    // preload k = 0 (stage A)
    {
        const float2* xr = &tb.xs[0][(ty ^ 0) * 4];
        xaA = *(const ulonglong2*)xr;
        xbA = *(const ulonglong2*)(xr + 2);
        wvA = *(const ulonglong2*)&tb.ws[0][(tx ^ 0) * 4];
    }
#pragma unroll
    for (int k = 0; k < BK; k += 2) {
        // load k+1 into stage B (issues ahead of stage-A FMAs)
        {
            const int kn = k + 1;
            const int sn = (kn >> 2) & 3;
            const float2* xr = &tb.xs[kn][(ty ^ sn) * 4];
            xaB = *(const ulonglong2*)xr;
            xbB = *(const ulonglong2*)(xr + 2);
            wvB = *(const ulonglong2*)&tb.ws[kn][(tx ^ (kn >> 2)) * 4];
        }
        if (SPL && k == SPLIT_KO) {   // global k == 1016: bank panel A, restart chain
#pragma unroll
            for (int t = 0; t < 4; ++t)
#pragma unroll
                for (int e = 0; e < 2; ++e) { accS[t][e] = acc[t][e]; acc[t][e] = 0ull; }
        }
        FMA8(acc, xaA, xbA, wvA);     // k
        if (k + 2 < BK) {             // load k+2 into stage A
            const int kn = k + 2;
            const int sn = (kn >> 2) & 3;
            const float2* xr = &tb.xs[kn][(ty ^ sn) * 4];
            xaA = *(const ulonglong2*)xr;
            xbA = *(const ulonglong2*)(xr + 2);
            wvA = *(const ulonglong2*)&tb.ws[kn][(tx ^ (kn >> 2)) * 4];
        }
        FMA8(acc, xaB, xbB, wvB);     // k+1
    }
}

__global__ __launch_bounds__(NTHREADS, 1)
void gate_kernel(const float* __restrict__ x, const float* __restrict__ wgt,
                 const float* __restrict__ bias, float* __restrict__ out,
                 int N, int D)
{
    extern __shared__ char smem_raw[];
    GateSm& sm = *reinterpret_cast<GateSm*>(smem_raw);

    const int tid  = threadIdx.x;
    const int tx   = tid & 15;    // experts 4tx .. 4tx+3
    const int ty   = tid >> 4;    // tokens  4ty .. 4ty+3  (0..31)
    const int row0 = blockIdx.x * BM;

    // gmem load mapping
    const int xtok = tid >> 2;    // 0..127, token
    const int xk4  = tid & 3;     // k-group of 4 (two passes: +0, +16)
    const int wex  = tid >> 3;    // 0..63, expert
    const int wk4  = tid & 7;     // k-group of 4
    const int wcol = (((wex >> 2) ^ wk4) << 2) | (wex & 3);   // conflict-free store col
    const int xcol = xtok ^ (xk4 * 4);

    // chain A (banked in accS) + chain B per (token, expert) lane — round-9 numerics
    unsigned long long acc[4][2], accS[4][2];
#pragma unroll
    for (int t = 0; t < 4; ++t)
#pragma unroll
        for (int e = 0; e < 2; ++e) { acc[t][e] = 0ull; accS[t][e] = 0ull; }

    const float* xptr = x + (size_t)(row0 + xtok) * D + xk4 * 4;
    const float* wptr = wgt + (size_t)wex * D + wk4 * 4;

    float4 rx0 = *(const float4*)xptr;
    float4 rx1 = *(const float4*)(xptr + 16);
    float4 rw  = *(const float4*)wptr;

    for (int ch = 0; ch < NCH; ++ch) {
        Tile& tb = sm.t[ch & 1];

        // store x transposed + duplicated + swizzled (two 16-k passes)
        tb.xs[xk4 * 4 + 0][xcol] = make_float2(rx0.x, rx0.x);
        tb.xs[xk4 * 4 + 1][xcol] = make_float2(rx0.y, rx0.y);
        tb.xs[xk4 * 4 + 2][xcol] = make_float2(rx0.z, rx0.z);
        tb.xs[xk4 * 4 + 3][xcol] = make_float2(rx0.w, rx0.w);
        tb.xs[16 + xk4 * 4 + 0][xcol] = make_float2(rx1.x, rx1.x);
        tb.xs[16 + xk4 * 4 + 1][xcol] = make_float2(rx1.y, rx1.y);
        tb.xs[16 + xk4 * 4 + 2][xcol] = make_float2(rx1.z, rx1.z);
        tb.xs[16 + xk4 * 4 + 3][xcol] = make_float2(rx1.w, rx1.w);
        // store w (swizzled column, conflict-free)
        tb.ws[wk4 * 4 + 0][wcol] = rw.x;
        tb.ws[wk4 * 4 + 1][wcol] = rw.y;
        tb.ws[wk4 * 4 + 2][wcol] = rw.z;
        tb.ws[wk4 * 4 + 3][wcol] = rw.w;
        __syncthreads();   // tile ch ready; buffer reuse is 2 syncs away

        // prefetch next chunk (overlaps with compute below)
        if (ch + 1 < NCH) {
            const int kc = (ch + 1) * BK;
            rx0 = *(const float4*)(xptr + kc);
            rx1 = *(const float4*)(xptr + kc + 16);
            rw  = *(const float4*)(wptr + kc);
        }

        if (ch == SPLIT_CH) compute_chunk<true >(tb, acc, accS, tx, ty);
        else                compute_chunk<false>(tb, acc, accS, tx, ty);
    }

    // logit = panel A + panel B (single packed FADD — round-9 order)
#pragma unroll
    for (int t = 0; t < 4; ++t)
#pragma unroll
        for (int e = 0; e < 2; ++e)
            ADD2(accS[t][e], acc[t][e]);

    __syncthreads();   // all compute done before aliasing tiles with scores

    // sigmoid -> scores in smem. accS[t][e]: lo = expert 4tx+2e, hi = 4tx+2e+1
#pragma unroll
    for (int t = 0; t < 4; ++t) {
#pragma unroll
        for (int e = 0; e < 2; ++e) {
            const unsigned long long a = accS[t][e];
            const float lo = __uint_as_float((unsigned)a);
            const float hi = __uint_as_float((unsigned)(a >> 32));
            sm.sc[4 * ty + t][4 * tx + 2 * e]     = sigmoid_cr(lo);
            sm.sc[4 * ty + t][4 * tx + 2 * e + 1] = sigmoid_cr(hi);
        }
    }
    __syncthreads();

    // top-8 per row: one warp per row, iterative warp-argmax (tie -> smaller index)
    const int lane = tid & 31;
    const int wid  = tid >> 5;   // 0..15
    const float b0 = __ldg(&bias[lane]);
    const float b1 = __ldg(&bias[lane + 32]);
    float* outw = out;
    float* outi = out + (size_t)N * TOPK_;

    for (int rr = wid; rr < BM; rr += 16) {
        const float s0 = sm.sc[rr][lane];
        const float s1 = sm.sc[rr][lane + 32];
        float r0 = __fadd_rn(s0, b0);
        float r1 = __fadd_rn(s1, b1);

        float wsel[TOPK_];
        int   isel[TOPK_];
        float sum = 0.0f;

#pragma unroll
        for (int t = 0; t < TOPK_; ++t) {
            float v; int i;
            if (r1 > r0) { v = r1; i = lane + 32; } else { v = r0; i = lane; }
#pragma unroll
            for (int off = 16; off > 0; off >>= 1) {
                const float vo = __shfl_down_sync(0xffffffffu, v, off);
                const int   io = __shfl_down_sync(0xffffffffu, i, off);
                if (vo > v || (vo == v && io < i)) { v = vo; i = io; }
            }
            i = __shfl_sync(0xffffffffu, i, 0);
            if (i == lane)      r0 = -FLT_MAX;
            if (i == lane + 32) r1 = -FLT_MAX;
            const float orig = sm.sc[rr][i];        // original (un-biased) sigmoid score
            isel[t] = i;
            wsel[t] = orig;
            sum = __fadd_rn(sum, orig);             // sequential last-axis sum like reference
        }

        const float denom = __fadd_rn(sum, 1e-8f);  // (w / (sum+1e-8)) * 2.5, ref op order
        const int grow = row0 + rr;
#pragma unroll
        for (int t = 0; t < TOPK_; ++t) {
            if (lane == t) {
                outw[(size_t)grow * TOPK_ + t] = __fmul_rn(__fdiv_rn(wsel[t], denom), 2.5f);
                outi[(size_t)grow * TOPK_ + t] = (float)isel[t];
            }
        }
    }
}

extern "C" void kernel_launch(void* const* d_in, const int* in_sizes, int n_in,
                              void* d_out, int out_size)
{
    const float* x = (const float*)d_in[0];
    const float* w = (const float*)d_in[1];
    const float* b = (const float*)d_in[2];

    const int E = in_sizes[2];          // 64
    const int D = in_sizes[1] / E;      // 2048
    const int N = in_sizes[0] / D;      // 16384
    (void)n_in; (void)out_size; (void)E;

    const int smem_bytes = (int)sizeof(GateSm);    // 80 KB (dynamic)
    cudaFuncSetAttribute(gate_kernel, cudaFuncAttributeMaxDynamicSharedMemorySize, smem_bytes);

    dim3 grid(N / BM);
    gate_kernel<<<grid, NTHREADS, smem_bytes>>>(x, w, b, (float*)d_out, N, D);
}